// round 15
// baseline (speedup 1.0000x reference)
#include <cuda_runtime.h>
#include <cuda_fp16.h>
#include <cstdint>

#define BATCH 8192
#define DIN   768
#define DSAE  12288
#define KTOP  64
#define CANDMAX 128

// ---------------- scratch (__device__ globals = sanctioned scratch) --------
__device__ float g_cvals[BATCH * KTOP];
__device__ int   g_cidx [BATCH * KTOP];
__device__ int   g_G    [BATCH];
__device__ int   g_C    [BATCH];
__device__ int   g_need [BATCH];
__device__ int   g_cand [BATCH * CANDMAX];

// fp16 operands, K-major
__device__ __half g_A[BATCH * DIN];            // x - b_dec
__device__ __half g_B[DSAE * DIN];             // W_enc^T  [n][k]
// fp32 transposed encoder weights for refine
__device__ float g_WeT[(size_t)DSAE * DIN];

__device__ __forceinline__ uint32_t smem_u32(const void* p) {
    uint32_t a;
    asm("{ .reg .u64 t; cvta.to.shared.u64 t, %1; cvt.u32.u64 %0, t; }"
        : "=r"(a) : "l"(p));
    return a;
}
__device__ __forceinline__ void ldsm4(uint32_t* r, uint32_t addr) {
    asm volatile("ldmatrix.sync.aligned.m8n8.x4.shared.b16 {%0,%1,%2,%3}, [%4];"
                 : "=r"(r[0]), "=r"(r[1]), "=r"(r[2]), "=r"(r[3]) : "r"(addr));
}
__device__ __forceinline__ void mma16816h(float* c, const uint32_t* a, const uint32_t* b) {
    asm volatile(
        "mma.sync.aligned.m16n8k16.row.col.f32.f16.f16.f32 "
        "{%0,%1,%2,%3}, {%4,%5,%6,%7}, {%8,%9}, {%0,%1,%2,%3};"
        : "+f"(c[0]), "+f"(c[1]), "+f"(c[2]), "+f"(c[3])
        : "r"(a[0]), "r"(a[1]), "r"(a[2]), "r"(a[3]), "r"(b[0]), "r"(b[1]));
}
__device__ __forceinline__ void cp16(uint32_t saddr, const void* g) {
    asm volatile("cp.async.cg.shared.global [%0], [%1], 16;" :: "r"(saddr), "l"(g));
}

// ---------------------------------------------------------------------------
__global__ __launch_bounds__(256)
void convA(const float* __restrict__ x, const float* __restrict__ bd)
{
    int idx = blockIdx.x * 256 + threadIdx.x;
    if (idx >= BATCH * DIN) return;
    int k = idx % DIN;
    g_A[idx] = __float2half(x[idx] - bd[k]);
}

__global__ __launch_bounds__(256)
void convB(const float* __restrict__ We)
{
    __shared__ float tile[32][33];
    int tx = threadIdx.x & 31, ty = threadIdx.x >> 5;
    int nBase = blockIdx.x * 32;
    int kBase = blockIdx.y * 32;
#pragma unroll
    for (int r = 0; r < 4; r++)
        tile[ty + r * 8][tx] = We[(size_t)(kBase + ty + r * 8) * DSAE + nBase + tx];
    __syncthreads();
#pragma unroll
    for (int r = 0; r < 4; r++) {
        int n = nBase + ty + r * 8;
        int k = kBase + tx;
        float v = tile[tx][ty + r * 8];
        g_B  [(size_t)n * DIN + k] = __float2half(v);
        g_WeT[(size_t)n * DIN + k] = v;
    }
}

// ---------------------------------------------------------------------------
// Kernel 1: encoder GEMM, fp16 mma.sync, BM=256 BN=128 BK=64, 3-stage
// cp.async pipeline. 8 warps as 4m x 2n, warp tile 64x64.
// L2 operand traffic: 1.8 GB (vs 2.4 GB at 128x128).
// ---------------------------------------------------------------------------
#define PADH 72                       // half row stride (144B)
#define ABYTES (256 * PADH * 2)       // 36864 B A tile per stage
#define BBYTES (128 * PADH * 2)       // 18432 B B tile per stage
#define STAGEB (ABYTES + BBYTES)      // 55296 B
#define NSTAGE 3
#define GEMM_SMEM (NSTAGE * STAGEB)   // 165888 B

__global__ __launch_bounds__(256, 1)
void enc_gemm_mma(const float* __restrict__ be, float* __restrict__ pre)
{
    extern __shared__ char dsm[];
    const uint32_t sb = smem_u32(dsm);

    const int tid  = threadIdx.x;
    const int lane = tid & 31;
    const int wid  = tid >> 5;
    const int warpM = (wid >> 1) * 64;     // 4 m-warps
    const int warpN = (wid & 1) * 64;      // 2 n-warps
    const int mBase = blockIdx.y * 256;
    const int nBase = blockIdx.x * 128;

    float acc[4][8][4];
#pragma unroll
    for (int i = 0; i < 4; i++)
#pragma unroll
        for (int j = 0; j < 8; j++)
#pragma unroll
            for (int v = 0; v < 4; v++) acc[i][j][v] = 0.f;

    // per chunk: A = 2048 x 16B ops (8/thread), B = 1024 (4/thread)
#define ISSUE_CHUNK(c, stage)                                                   \
    {                                                                           \
        int kof = (c) * 64;                                                     \
        uint32_t st = sb + (stage) * STAGEB;                                    \
        _Pragma("unroll")                                                       \
        for (int p = 0; p < 8; p++) {                                           \
            int id  = tid + p * 256;                                            \
            int row = id >> 3, seg = id & 7;                                    \
            uint32_t so = (uint32_t)(row * PADH + seg * 8) * 2;                 \
            size_t ga = (size_t)(mBase + row) * DIN + kof + seg * 8;            \
            cp16(st + so, g_A + ga);                                            \
        }                                                                       \
        _Pragma("unroll")                                                       \
        for (int p = 0; p < 4; p++) {                                           \
            int id  = tid + p * 256;                                            \
            int row = id >> 3, seg = id & 7;                                    \
            uint32_t so = (uint32_t)(row * PADH + seg * 8) * 2;                 \
            size_t gb = (size_t)(nBase + row) * DIN + kof + seg * 8;            \
            cp16(st + ABYTES + so, g_B + gb);                                   \
        }                                                                       \
    }

    const int aRow = lane & 15;
    const int aCol = (lane >> 4) * 8;
    const int bg   = lane >> 3;
    const int bRowOff = ((bg >> 1) * 8) + (lane & 7);
    const int bColOff = (bg & 1) * 8;

    ISSUE_CHUNK(0, 0);
    asm volatile("cp.async.commit_group;" ::: "memory");
    ISSUE_CHUNK(1, 1);
    asm volatile("cp.async.commit_group;" ::: "memory");

    for (int c = 0; c < DIN / 64; c++) {          // 12 chunks
        asm volatile("cp.async.wait_group 1;" ::: "memory");
        __syncthreads();

        if (c + 2 < DIN / 64) {
            ISSUE_CHUNK(c + 2, (c + 2) % NSTAGE);
            asm volatile("cp.async.commit_group;" ::: "memory");
        }

        uint32_t st = sb + (c % NSTAGE) * STAGEB;
        uint32_t uA = st, uB = st + ABYTES;

#pragma unroll
        for (int ks = 0; ks < 4; ks++) {
            uint32_t a[4][4];
#pragma unroll
            for (int mt = 0; mt < 4; mt++) {
                uint32_t off = (uint32_t)((warpM + mt * 16 + aRow) * PADH +
                                          ks * 16 + aCol) * 2;
                ldsm4(a[mt], uA + off);
            }
            uint32_t b[8][2];
#pragma unroll
            for (int i = 0; i < 4; i++) {
                uint32_t off = (uint32_t)((warpN + i * 16 + bRowOff) * PADH +
                                          bColOff + ks * 16) * 2;
                uint32_t t[4];
                ldsm4(t, uB + off);
                b[2 * i][0] = t[0]; b[2 * i][1] = t[1];
                b[2 * i + 1][0] = t[2]; b[2 * i + 1][1] = t[3];
            }
#pragma unroll
            for (int mt = 0; mt < 4; mt++)
#pragma unroll
                for (int nt = 0; nt < 8; nt++)
                    mma16816h(acc[mt][nt], a[mt], b[nt]);
        }
        __syncthreads();
    }

    // epilogue: +b_enc, relu, store
#pragma unroll
    for (int mt = 0; mt < 4; mt++) {
#pragma unroll
        for (int nt = 0; nt < 8; nt++) {
            int m0 = mBase + warpM + mt * 16 + (lane >> 2);
            int n0 = nBase + warpN + nt * 8 + (lane & 3) * 2;
            float2 bev = *(const float2*)(be + n0);
            float2 o;
            o.x = fmaxf(acc[mt][nt][0] + bev.x, 0.f);
            o.y = fmaxf(acc[mt][nt][1] + bev.y, 0.f);
            *(float2*)(pre + (size_t)m0 * DSAE + n0) = o;
            o.x = fmaxf(acc[mt][nt][2] + bev.x, 0.f);
            o.y = fmaxf(acc[mt][nt][3] + bev.y, 0.f);
            *(float2*)(pre + (size_t)(m0 + 8) * DSAE + n0) = o;
        }
    }
}

// ---------------------------------------------------------------------------
// block exclusive scan over 256 threads (shfl + 8 warp partials)
// ---------------------------------------------------------------------------
__device__ __forceinline__ unsigned block_scan_excl(unsigned v, unsigned* wsum,
                                                    unsigned& total)
{
    const int lane = threadIdx.x & 31, w = threadIdx.x >> 5;
    unsigned incl = v;
#pragma unroll
    for (int o = 1; o < 32; o <<= 1) {
        unsigned n = __shfl_up_sync(0xffffffffu, incl, o);
        if (lane >= o) incl += n;
    }
    if (lane == 31) wsum[w] = incl;
    __syncthreads();
    if (w == 0) {
        unsigned s = (lane < 8) ? wsum[lane] : 0u;
#pragma unroll
        for (int o = 1; o < 8; o <<= 1) {
            unsigned n = __shfl_up_sync(0xffffffffu, s, o);
            if (lane >= o) s += n;
        }
        if (lane < 8) wsum[lane] = s;
    }
    __syncthreads();
    unsigned base = w ? wsum[w - 1] : 0u;
    total = wsum[7];
    return base + incl - v;
}

// ---------------------------------------------------------------------------
// Kernel 2: streaming per-row top-64, TWO 12-bit radix passes (4096-bin
// hist). Threshold truncated to bits [30:7] — granularity 1.5e-5 rel, far
// inside the 4e-3 margin band, so classification semantics are unchanged.
// ---------------------------------------------------------------------------
__global__ __launch_bounds__(256)
void topk_kernel(float* __restrict__ sparse)
{
    __shared__ unsigned hist[4096];        // 16 KB
    __shared__ unsigned wsum[8];
    __shared__ unsigned sh_bin, sh_need;

    const int r   = blockIdx.x;
    const int tid = threadIdx.x;
    float* src = sparse + (size_t)r * DSAE;
    const float4* s4 = (const float4*)src;

    unsigned sel = 0, selmask = 0;
    int kneed = KTOP;
#pragma unroll
    for (int pass = 0; pass < 2; pass++) {
        const int shift = pass ? 7 : 19;
        for (int i = tid; i < 4096; i += 256) hist[i] = 0;
        __syncthreads();
#pragma unroll 2
        for (int j = 0; j < 12; j++) {
            float4 f = s4[j * 256 + tid];
            unsigned u;
            u = __float_as_uint(f.x); if ((u & selmask) == sel) atomicAdd(&hist[(u >> shift) & 0xFFFu], 1u);
            u = __float_as_uint(f.y); if ((u & selmask) == sel) atomicAdd(&hist[(u >> shift) & 0xFFFu], 1u);
            u = __float_as_uint(f.z); if ((u & selmask) == sel) atomicAdd(&hist[(u >> shift) & 0xFFFu], 1u);
            u = __float_as_uint(f.w); if ((u & selmask) == sel) atomicAdd(&hist[(u >> shift) & 0xFFFu], 1u);
        }
        __syncthreads();
        // descending 16-bin groups: thread t owns bins [4095-16t .. 4080-16t]
        unsigned lsum = 0;
        int bTop = 4095 - 16 * tid;
#pragma unroll
        for (int j = 0; j < 16; j++) lsum += hist[bTop - j];
        unsigned total, above = block_scan_excl(lsum, wsum, total);
        if ((int)above < kneed && (int)(above + lsum) >= kneed) {
            unsigned cum = above;
            for (int j = 0; j < 16; j++) {
                unsigned h = hist[bTop - j];
                cum += h;
                if ((int)cum >= kneed) {
                    sh_bin  = (unsigned)(bTop - j);
                    sh_need = (unsigned)(kneed - (int)(cum - h));
                    break;
                }
            }
        }
        __syncthreads();
        sel     |= sh_bin << shift;
        selmask |= 0xFFFu << shift;
        kneed    = (int)sh_need;
        __syncthreads();
    }

    const float t = __uint_as_float(sel);   // truncated threshold (<= exact T)

    // ---- margin classification (4e-3: fp16 GEMM noise = ~25 sigma) ----
    float m = t * 4e-3f;
    float hi = t + m, lo = t - m;
    unsigned hiBase = 0, cdBase = 0, G = 0, C = 0;

    for (int attempt = 0; attempt < 2; attempt++) {
        unsigned cHi = 0, cCd = 0;
#pragma unroll 2
        for (int j = 0; j < 12; j++) {
            float4 f = s4[j * 256 + tid];
            cHi += (f.x > hi) + (f.y > hi) + (f.z > hi) + (f.w > hi);
            cCd += ((f.x >= lo) & (f.x <= hi)) + ((f.y >= lo) & (f.y <= hi))
                 + ((f.z >= lo) & (f.z <= hi)) + ((f.w >= lo) & (f.w <= hi));
        }
        unsigned mine = (cHi << 16) | cCd;
        unsigned total, excl = block_scan_excl(mine, wsum, total);
        hiBase = excl >> 16;  cdBase = excl & 0xffffu;
        G = total >> 16;      C = total & 0xffffu;
        if (C <= CANDMAX) break;
        hi = t; lo = t;
        __syncthreads();
    }

    // ---- write pass ----
    int localHi = 0, localCd = 0;
#pragma unroll 2
    for (int j = 0; j < 12; j++) {
        int q = j * 256 + tid;
        float4 f = s4[q];
        float4 o;
        float* fe = &f.x;
        float* oe = &o.x;
#pragma unroll
        for (int e = 0; e < 4; e++) {
            float v = fe[e];
            int idx = q * 4 + e;
            if (v > hi) {
                int slot = (int)hiBase + localHi;
                g_cvals[r * KTOP + slot] = v;
                g_cidx [r * KTOP + slot] = idx;
                localHi++;
                oe[e] = v;
            } else if (v >= lo) {
                int cpos = (int)cdBase + localCd;
                if (cpos < CANDMAX) g_cand[r * CANDMAX + cpos] = idx;
                localCd++;
                oe[e] = v;          // refine resolves
            } else {
                oe[e] = 0.f;
            }
        }
        ((float4*)src)[q] = o;
    }

    if (tid == 0) {
        int Cc = (int)C;
        if (Cc > CANDMAX) Cc = CANDMAX;
        g_G[r]    = (int)G;
        g_C[r]    = Cc;
        g_need[r] = KTOP - (int)G;
    }
}

// ---------------------------------------------------------------------------
// Kernel 2b: Eigen-exact candidate rescoring, k-panels {320,320,128}.
// (correctness anchor — arithmetic untouched)
// ---------------------------------------------------------------------------
__global__ __launch_bounds__(128)
void refine_kernel(const float* __restrict__ x,
                   const float* __restrict__ be,
                   const float* __restrict__ bd,
                   float* __restrict__ sparse)
{
    __shared__ float cval[CANDMAX];
    __shared__ int   cidx[CANDMAX];
    __shared__ float xs[DIN];

    const int r    = blockIdx.x;
    const int tid  = threadIdx.x;

    const int G    = g_G[r];
    const int C    = g_C[r];
    const int need = g_need[r];

    for (int k = tid; k < DIN; k += 128)
        xs[k] = x[(size_t)r * DIN + k] - bd[k];
    if (tid < C) cidx[tid] = g_cand[r * CANDMAX + tid];
    __syncthreads();

    if (tid < C) {
        const int col = cidx[tid];
        const float* w = g_WeT + (size_t)col * DIN;
        const int kcs[4] = {0, 320, 640, 768};
        float master = 0.f;
#pragma unroll 1
        for (int c = 0; c < 3; c++) {
            float chunk = 0.f;
#pragma unroll 4
            for (int k = kcs[c]; k < kcs[c + 1]; k++)
                chunk = fmaf(xs[k], w[k], chunk);
            master = master + chunk;
        }
        master = master + be[col];
        cval[tid] = fmaxf(master, 0.f);
    }
    __syncthreads();

    if (tid < C) {
        float v = cval[tid];
        int   i = cidx[tid];
        unsigned u = __float_as_uint(v);
        int rank = 0;
        for (int k = 0; k < C; k++) {
            unsigned uk = __float_as_uint(cval[k]);
            rank += (uk > u) || (uk == u && cidx[k] < i);
        }
        float* src = sparse + (size_t)r * DSAE;
        if (rank < need) {
            src[i] = v;
            int slot = G + rank;
            g_cvals[r * KTOP + slot] = v;
            g_cidx [r * KTOP + slot] = i;
        } else {
            src[i] = 0.f;
        }
    }
}

// ---------------------------------------------------------------------------
// Kernel 3: sparse decode (unchanged)
// ---------------------------------------------------------------------------
__global__ __launch_bounds__(256)
void decode_kernel(const float* __restrict__ Wd,
                   const float* __restrict__ bd,
                   float* __restrict__ recon)
{
    __shared__ float sv[KTOP];
    __shared__ int   si[KTOP];
    const int r   = blockIdx.x;
    const int tid = threadIdx.x;
    if (tid < KTOP) {
        sv[tid] = g_cvals[r * KTOP + tid];
        si[tid] = g_cidx [r * KTOP + tid];
    }
    __syncthreads();

    float a0 = bd[tid];
    float a1 = bd[tid + 256];
    float a2 = bd[tid + 512];
#pragma unroll 4
    for (int j = 0; j < KTOP; j++) {
        const float* w = Wd + (size_t)si[j] * DIN;
        float v = sv[j];
        a0 = fmaf(v, w[tid],       a0);
        a1 = fmaf(v, w[tid + 256], a1);
        a2 = fmaf(v, w[tid + 512], a2);
    }
    float* out = recon + (size_t)r * DIN;
    out[tid]       = a0;
    out[tid + 256] = a1;
    out[tid + 512] = a2;
}

// ---------------------------------------------------------------------------
extern "C" void kernel_launch(void* const* d_in, const int* in_sizes, int n_in,
                              void* d_out, int out_size)
{
    const float* x  = (const float*)d_in[0];
    const float* We = (const float*)d_in[1];
    const float* be = (const float*)d_in[2];
    const float* Wd = (const float*)d_in[3];
    const float* bd = (const float*)d_in[4];

    float* out    = (float*)d_out;
    float* recon  = out;
    float* sparse = out + (size_t)BATCH * DIN;

    cudaFuncSetAttribute(enc_gemm_mma,
                         cudaFuncAttributeMaxDynamicSharedMemorySize, GEMM_SMEM);

    convA<<<(BATCH * DIN + 255) / 256, 256>>>(x, bd);
    convB<<<dim3(DSAE / 32, DIN / 32), 256>>>(We);

    dim3 gemm_grid(DSAE / 128, BATCH / 256);   // (96, 32)
    enc_gemm_mma<<<gemm_grid, 256, GEMM_SMEM>>>(be, sparse);

    topk_kernel<<<BATCH, 256>>>(sparse);
    refine_kernel<<<BATCH, 128>>>(x, be, bd, sparse);
    decode_kernel<<<BATCH, 256>>>(Wd, bd, recon);
}